// round 3
// baseline (speedup 1.0000x reference)
#include <cuda_runtime.h>

// CRF forward (log-partition) + gold path score, fused, scaled-linear-domain.
// B=4096 sequences, L=1024 steps, T=32 tags. One 32-thread CTA handles 4
// batches (two f32x2 packed pairs). Thread t owns state "next=t" and holds
// E[t][p]=exp(trans[t,p]) packed {e,e} in registers. fv exchanged via
// double-buffered SMEM broadcast loads; renormalized by exact powers of two
// every 4 steps.

namespace {

constexpr int T_ = 32;
constexpr int L_ = 1024;
constexpr int START_ = 30;
constexpr int STOP_ = 31;
constexpr unsigned FULL_ = 0xffffffffu;

__device__ __forceinline__ unsigned long long pack2(float lo, float hi) {
    unsigned long long r;
    asm("mov.b64 %0, {%1, %2};" : "=l"(r) : "f"(lo), "f"(hi));
    return r;
}
__device__ __forceinline__ void unpack2(unsigned long long v, float& lo, float& hi) {
    asm("mov.b64 {%0, %1}, %2;" : "=f"(lo), "=f"(hi) : "l"(v));
}
__device__ __forceinline__ void fma2(unsigned long long& acc, unsigned long long a,
                                     unsigned long long b) {
    asm("fma.rn.f32x2 %0, %1, %2, %0;" : "+l"(acc) : "l"(a), "l"(b));
}
__device__ __forceinline__ unsigned long long add2(unsigned long long a, unsigned long long b) {
    unsigned long long r;
    asm("add.rn.f32x2 %0, %1, %2;" : "=l"(r) : "l"(a), "l"(b));
    return r;
}
__device__ __forceinline__ unsigned long long mul2(unsigned long long a, unsigned long long b) {
    unsigned long long r;
    asm("mul.rn.f32x2 %0, %1, %2;" : "=l"(r) : "l"(a), "l"(b));
    return r;
}

// Renormalize a packed pair by per-batch powers of two. Positive IEEE floats
// compare correctly as unsigned ints, so REDUX.MAX.U32 gives the warp max.
__device__ __forceinline__ void renorm_pair(unsigned long long& v, int& se0, int& se1) {
    unsigned lo = (unsigned)v;
    unsigned hi = (unsigned)(v >> 32);
    unsigned m0 = __reduce_max_sync(FULL_, lo);
    unsigned m1 = __reduce_max_sync(FULL_, hi);
    int e0 = (int)(m0 >> 23) - 127;
    int e1 = (int)(m1 >> 23) - 127;
    e0 = max(-64, min(e0, 120));
    e1 = max(-64, min(e1, 120));
    unsigned s0 = (unsigned)(127 - e0) << 23;   // 2^-e0
    unsigned s1 = (unsigned)(127 - e1) << 23;   // 2^-e1
    unsigned long long sc = (unsigned long long)s0 | ((unsigned long long)s1 << 32);
    v = mul2(v, sc);
    se0 += e0;
    se1 += e1;
}

__global__ void __launch_bounds__(32) crf_fwd(const float* __restrict__ feats,
                                              const float* __restrict__ trans,
                                              const unsigned* __restrict__ tagw,
                                              float* __restrict__ out) {
    const int t = threadIdx.x;
    const int b0 = blockIdx.x * 4;

    __shared__ __align__(16) unsigned long long sA[2][32];
    __shared__ __align__(16) unsigned long long sB[2][32];

    // E row for this thread's "next" index, packed {e,e}.
    unsigned long long E2[32];
#pragma unroll
    for (int p = 0; p < 32; ++p) {
        float e = __expf(__ldg(trans + t * T_ + p));
        E2[p] = pack2(e, e);
    }

    // Initial fv (linear domain): v[START]=1, else 0.
    {
        float vi = (t == START_) ? 1.0f : 0.0f;
        unsigned long long pv = pack2(vi, vi);
        sA[0][t] = pv;
        sB[0][t] = pv;
    }

    // Detect tag element width: int64 -> odd 32-bit words all zero (values<30).
    unsigned oddw = __ldg(tagw + 2 * t + 1);
    const int TS = __any_sync(FULL_, oddw != 0) ? 1 : 2;  // words per tag

    const float* fb0 = feats + ((size_t)(b0 + 0) * L_) * T_ + t;
    const float* fb1 = feats + ((size_t)(b0 + 1) * L_) * T_ + t;
    const float* fb2 = feats + ((size_t)(b0 + 2) * L_) * T_ + t;
    const float* fb3 = feats + ((size_t)(b0 + 3) * L_) * T_ + t;
    const unsigned* tb0 = tagw + (size_t)(b0 + 0) * L_ * TS;
    const unsigned* tb1 = tagw + (size_t)(b0 + 1) * L_ * TS;
    const unsigned* tb2 = tagw + (size_t)(b0 + 2) * L_ * TS;
    const unsigned* tb3 = tagw + (size_t)(b0 + 3) * L_ * TS;

    float fA[4][4], fB[4][4];         // [step][batch] feat prefetch (ping-pong)
    unsigned gA[4][4], gB[4][4];      // [step][batch] tag prefetch

    int sc0 = 0, sc1 = 0, sc2 = 0, sc3 = 0;               // log2 scale accumulators
    float ge0 = 0.f, ge1 = 0.f, ge2 = 0.f, ge3 = 0.f;     // gold emission partials
    float gt0 = 0.f, gt1 = 0.f, gt2 = 0.f, gt3 = 0.f;     // gold transition sums
    unsigned pv0 = START_, pv1 = START_, pv2 = START_, pv3 = START_;

#define PF(FB, GB, LBASE)                                                      \
    do {                                                                       \
        const int lb_ = (LBASE);                                               \
        const float* q0_ = fb0 + (size_t)lb_ * T_;                             \
        const float* q1_ = fb1 + (size_t)lb_ * T_;                             \
        const float* q2_ = fb2 + (size_t)lb_ * T_;                             \
        const float* q3_ = fb3 + (size_t)lb_ * T_;                             \
        const unsigned wb_ = (unsigned)(lb_ * TS);                             \
        _Pragma("unroll") for (int s_ = 0; s_ < 4; ++s_) {                     \
            FB[s_][0] = __ldg(q0_ + s_ * T_);                                  \
            FB[s_][1] = __ldg(q1_ + s_ * T_);                                  \
            FB[s_][2] = __ldg(q2_ + s_ * T_);                                  \
            FB[s_][3] = __ldg(q3_ + s_ * T_);                                  \
            const unsigned w_ = wb_ + (unsigned)(s_ * TS);                     \
            GB[s_][0] = __ldg(tb0 + w_);                                       \
            GB[s_][1] = __ldg(tb1 + w_);                                       \
            GB[s_][2] = __ldg(tb2 + w_);                                       \
            GB[s_][3] = __ldg(tb3 + w_);                                       \
        }                                                                      \
    } while (0)

#define STEP(FB, GB, S, CUR, NXT, RN)                                          \
    do {                                                                       \
        const float f0_ = FB[S][0], f1_ = FB[S][1];                            \
        const float f2_ = FB[S][2], f3_ = FB[S][3];                            \
        const unsigned long long ef01_ = pack2(__expf(f0_), __expf(f1_));      \
        const unsigned long long ef23_ = pack2(__expf(f2_), __expf(f3_));      \
        unsigned long long aa_[4] = {0ULL, 0ULL, 0ULL, 0ULL};                  \
        unsigned long long bb_[4] = {0ULL, 0ULL, 0ULL, 0ULL};                  \
        _Pragma("unroll") for (int p_ = 0; p_ < 32; p_ += 2) {                 \
            const ulonglong2 ua_ = *(const ulonglong2*)&sA[CUR][p_];           \
            const ulonglong2 ub_ = *(const ulonglong2*)&sB[CUR][p_];           \
            fma2(aa_[p_ & 3], ua_.x, E2[p_]);                                  \
            fma2(aa_[(p_ + 1) & 3], ua_.y, E2[p_ + 1]);                        \
            fma2(bb_[p_ & 3], ub_.x, E2[p_]);                                  \
            fma2(bb_[(p_ + 1) & 3], ub_.y, E2[p_ + 1]);                        \
        }                                                                      \
        unsigned long long vA_ =                                               \
            mul2(add2(add2(aa_[0], aa_[1]), add2(aa_[2], aa_[3])), ef01_);     \
        unsigned long long vB_ =                                               \
            mul2(add2(add2(bb_[0], bb_[1]), add2(bb_[2], bb_[3])), ef23_);     \
        if (RN) {                                                              \
            renorm_pair(vA_, sc0, sc1);                                        \
            renorm_pair(vB_, sc2, sc3);                                        \
        }                                                                      \
        sA[NXT][t] = vA_;                                                      \
        sB[NXT][t] = vB_;                                                      \
        const unsigned g0_ = GB[S][0], g1_ = GB[S][1];                         \
        const unsigned g2_ = GB[S][2], g3_ = GB[S][3];                         \
        gt0 += __ldg(trans + g0_ * 32u + pv0); pv0 = g0_;                      \
        gt1 += __ldg(trans + g1_ * 32u + pv1); pv1 = g1_;                      \
        gt2 += __ldg(trans + g2_ * 32u + pv2); pv2 = g2_;                      \
        gt3 += __ldg(trans + g3_ * 32u + pv3); pv3 = g3_;                      \
        ge0 += (t == (int)g0_) ? f0_ : 0.0f;                                   \
        ge1 += (t == (int)g1_) ? f1_ : 0.0f;                                   \
        ge2 += (t == (int)g2_) ? f2_ : 0.0f;                                   \
        ge3 += (t == (int)g3_) ? f3_ : 0.0f;                                   \
        __syncthreads();                                                       \
    } while (0)

    PF(fA, gA, 0);
    __syncthreads();  // init stores visible

#pragma unroll 1
    for (int g2 = 0; g2 < 128; ++g2) {
        const int lb = g2 * 8;
        PF(fB, gB, lb + 4);
        STEP(fA, gA, 0, 0, 1, false);
        STEP(fA, gA, 1, 1, 0, false);
        STEP(fA, gA, 2, 0, 1, false);
        STEP(fA, gA, 3, 1, 0, true);
        if (g2 < 127) PF(fA, gA, lb + 8);
        STEP(fB, gB, 0, 0, 1, false);
        STEP(fB, gB, 1, 1, 0, false);
        STEP(fB, gB, 2, 0, 1, false);
        STEP(fB, gB, 3, 1, 0, true);
    }
#undef PF
#undef STEP

    // ---- epilogue: alpha = log( sum_t v[t]*exp(trans[STOP,t]) ) + sc*ln2 ----
    unsigned long long vA = sA[0][t];
    unsigned long long vB = sB[0][t];
    {
        const float es = __expf(__ldg(trans + STOP_ * T_ + t));
        const unsigned long long es2 = pack2(es, es);
        vA = mul2(vA, es2);
        vB = mul2(vB, es2);
    }
#pragma unroll
    for (int o = 16; o > 0; o >>= 1) {
        vA = add2(vA, __shfl_xor_sync(FULL_, vA, o));
        vB = add2(vB, __shfl_xor_sync(FULL_, vB, o));
    }
    unsigned long long gep01 = pack2(ge0, ge1);
    unsigned long long gep23 = pack2(ge2, ge3);
#pragma unroll
    for (int o = 16; o > 0; o >>= 1) {
        gep01 = add2(gep01, __shfl_xor_sync(FULL_, gep01, o));
        gep23 = add2(gep23, __shfl_xor_sync(FULL_, gep23, o));
    }

    if (t == 0) {
        float z0, z1, z2, z3, e0, e1, e2, e3;
        unpack2(vA, z0, z1);
        unpack2(vB, z2, z3);
        unpack2(gep01, e0, e1);
        unpack2(gep23, e2, e3);
        const float LN2 = 0.6931471805599453f;
        const float a0 = __logf(z0) + (float)sc0 * LN2;
        const float a1 = __logf(z1) + (float)sc1 * LN2;
        const float a2 = __logf(z2) + (float)sc2 * LN2;
        const float a3 = __logf(z3) + (float)sc3 * LN2;
        const float go0 = gt0 + e0 + __ldg(trans + STOP_ * 32u + pv0);
        const float go1 = gt1 + e1 + __ldg(trans + STOP_ * 32u + pv1);
        const float go2 = gt2 + e2 + __ldg(trans + STOP_ * 32u + pv2);
        const float go3 = gt3 + e3 + __ldg(trans + STOP_ * 32u + pv3);
        float4 r = make_float4(a0 - go0, a1 - go1, a2 - go2, a3 - go3);
        *(float4*)(out + b0) = r;
    }
}

}  // namespace

extern "C" void kernel_launch(void* const* d_in, const int* in_sizes, int n_in,
                              void* d_out, int out_size) {
    const float* feats = (const float*)d_in[0];
    const float* trans = (const float*)d_in[1];
    const unsigned* tagw = (const unsigned*)d_in[2];  // int32 or int64 tags (detected in-kernel)
    float* out = (float*)d_out;

    const int B = in_sizes[2] / L_;  // element count = B*L regardless of tag dtype
    crf_fwd<<<B / 4, 32>>>(feats, trans, tagw, out);
}

// round 4
// speedup vs baseline: 1.3661x; 1.3661x over previous
#include <cuda_runtime.h>

// Linear-chain CRF NLL, fused forward (log-partition) + gold score.
// B=4096, L=1024, T=32. One 32-thread warp-block handles 2 batches packed as
// f32x2. Thread t owns next-state t; E[t][p]=exp(trans[t,p]) in registers
// (p=0..29 only; p=30 (START) handled by closed-form step 0, p=31 (STOP)
// column is exactly 0). fv exchanged via double-buffered SMEM broadcast,
// renormalized by exact powers of two every 4 steps. 3-deep register prefetch
// (distance 8 steps). __launch_bounds__(32,14) -> single wave of 2048 warps.

namespace {

constexpr int T_ = 32;
constexpr int L_ = 1024;
constexpr int START_ = 30;
constexpr int STOP_ = 31;
constexpr unsigned FULL_ = 0xffffffffu;
typedef unsigned long long u64;

__device__ __forceinline__ u64 pack2(float lo, float hi) {
    u64 r;
    asm("mov.b64 %0, {%1, %2};" : "=l"(r) : "f"(lo), "f"(hi));
    return r;
}
__device__ __forceinline__ void unpack2(u64 v, float& lo, float& hi) {
    asm("mov.b64 {%0, %1}, %2;" : "=f"(lo), "=f"(hi) : "l"(v));
}
__device__ __forceinline__ void fma2(u64& acc, u64 a, u64 b) {
    asm("fma.rn.f32x2 %0, %1, %2, %0;" : "+l"(acc) : "l"(a), "l"(b));
}
__device__ __forceinline__ u64 add2(u64 a, u64 b) {
    u64 r;
    asm("add.rn.f32x2 %0, %1, %2;" : "=l"(r) : "l"(a), "l"(b));
    return r;
}
__device__ __forceinline__ u64 mul2(u64 a, u64 b) {
    u64 r;
    asm("mul.rn.f32x2 %0, %1, %2;" : "=l"(r) : "l"(a), "l"(b));
    return r;
}

// Exact power-of-two renormalization; positive floats compare as unsigned ints.
__device__ __forceinline__ void renorm_pair(u64& v, int& se0, int& se1) {
    unsigned lo = (unsigned)v;
    unsigned hi = (unsigned)(v >> 32);
    unsigned m0 = __reduce_max_sync(FULL_, lo);
    unsigned m1 = __reduce_max_sync(FULL_, hi);
    int e0 = (int)(m0 >> 23) - 127;
    int e1 = (int)(m1 >> 23) - 127;
    e0 = max(-64, min(e0, 120));
    e1 = max(-64, min(e1, 120));
    unsigned s0 = (unsigned)(127 - e0) << 23;  // 2^-e0
    unsigned s1 = (unsigned)(127 - e1) << 23;  // 2^-e1
    v = mul2(v, (u64)s0 | ((u64)s1 << 32));
    se0 += e0;
    se1 += e1;
}

template <int TS>
__device__ __forceinline__ void crf_body(const float* __restrict__ feats,
                                         const float* __restrict__ trans,
                                         const unsigned* __restrict__ tagw,
                                         float* __restrict__ out,
                                         u64 (*sv)[32]) {
    const int t = threadIdx.x;
    const int b0 = blockIdx.x * 2;

    // E row, prev states 0..29 packed {e,e}; START column kept scalar.
    u64 E2[30];
#pragma unroll
    for (int p = 0; p < 30; ++p) {
        float e = __expf(__ldg(trans + t * T_ + p));
        E2[p] = pack2(e, e);
    }
    const float e30 = __expf(__ldg(trans + t * T_ + START_));

    const float* fb0 = feats + (size_t)b0 * L_ * T_ + t;
    const float* fb1 = fb0 + (size_t)L_ * T_;
    const unsigned* tb0 = tagw + (size_t)b0 * L_ * TS;
    const unsigned* tb1 = tb0 + (size_t)L_ * TS;

    float F0[3][4], F1[3][4];  // feat prefetch [buf][step]
    unsigned P0[3], P1[3];     // 4 tags byte-packed per buf per batch

    int sc0 = 0, sc1 = 0;
    float gt0 = 0.f, gt1 = 0.f, ge0 = 0.f, ge1 = 0.f;
    unsigned pv0 = START_, pv1 = START_;

#define PF(I, G)                                                               \
    do {                                                                       \
        const int gc_ = ((G) < 256) ? (G) : 255;                               \
        const float* q0_ = fb0 + gc_ * 128;                                    \
        const float* q1_ = fb1 + gc_ * 128;                                    \
        _Pragma("unroll") for (int s_ = 0; s_ < 4; ++s_) {                     \
            F0[I][s_] = __ldg(q0_ + s_ * 32);                                  \
            F1[I][s_] = __ldg(q1_ + s_ * 32);                                  \
        }                                                                      \
        if (TS == 1) {                                                         \
            uint4 w0_ = __ldg((const uint4*)(tb0 + gc_ * 4));                  \
            uint4 w1_ = __ldg((const uint4*)(tb1 + gc_ * 4));                  \
            P0[I] = w0_.x | (w0_.y << 8) | (w0_.z << 16) | (w0_.w << 24);      \
            P1[I] = w1_.x | (w1_.y << 8) | (w1_.z << 16) | (w1_.w << 24);      \
        } else {                                                               \
            uint4 a0_ = __ldg((const uint4*)(tb0 + gc_ * 8));                  \
            uint4 a1_ = __ldg((const uint4*)(tb0 + gc_ * 8 + 4));              \
            uint4 c0_ = __ldg((const uint4*)(tb1 + gc_ * 8));                  \
            uint4 c1_ = __ldg((const uint4*)(tb1 + gc_ * 8 + 4));              \
            P0[I] = a0_.x | (a0_.z << 8) | (a1_.x << 16) | (a1_.z << 24);      \
            P1[I] = c0_.x | (c0_.z << 8) | (c1_.x << 16) | (c1_.z << 24);      \
        }                                                                      \
    } while (0)

#define GOLD(I, S, FV0, FV1)                                                   \
    do {                                                                       \
        const unsigned g0_ = (P0[I] >> (8 * (S))) & 0xffu;                     \
        const unsigned g1_ = (P1[I] >> (8 * (S))) & 0xffu;                     \
        gt0 += __ldg(trans + g0_ * 32u + pv0);                                 \
        pv0 = g0_;                                                             \
        gt1 += __ldg(trans + g1_ * 32u + pv1);                                 \
        pv1 = g1_;                                                             \
        ge0 += (t == (int)g0_) ? (FV0) : 0.0f;                                 \
        ge1 += (t == (int)g1_) ? (FV1) : 0.0f;                                 \
    } while (0)

#define STEP(I, S, CUR, NXT, RN)                                               \
    do {                                                                       \
        const float f0_ = F0[I][S], f1_ = F1[I][S];                            \
        const u64 ef_ = pack2(__expf(f0_), __expf(f1_));                       \
        u64 a_[4] = {0ULL, 0ULL, 0ULL, 0ULL};                                  \
        _Pragma("unroll") for (int j_ = 0; j_ < 15; ++j_) {                    \
            const ulonglong2 u_ = *(const ulonglong2*)&sv[CUR][2 * j_];        \
            fma2(a_[(2 * j_) & 3], u_.x, E2[2 * j_]);                          \
            fma2(a_[(2 * j_ + 1) & 3], u_.y, E2[2 * j_ + 1]);                  \
        }                                                                      \
        u64 v_ = mul2(add2(add2(a_[0], a_[1]), add2(a_[2], a_[3])), ef_);      \
        if (RN) renorm_pair(v_, sc0, sc1);                                     \
        sv[NXT][t] = v_;                                                       \
        GOLD(I, S, f0_, f1_);                                                  \
        __syncthreads();                                                       \
    } while (0)

#define GROUP(I)                                                               \
    do {                                                                       \
        STEP(I, 0, 1, 0, false);                                               \
        STEP(I, 1, 0, 1, false);                                               \
        STEP(I, 2, 1, 0, false);                                               \
        STEP(I, 3, 0, 1, true);                                                \
    } while (0)

    // Prologue: fill all three prefetch buffers (groups 0, 1, 2).
    PF(0, 0);
    PF(1, 1);
    PF(2, 2);

    // Group 0: step l=0 is the closed form v1[t] = exp(trans[t,START])*exp(f0).
    {
        const float f0_ = F0[0][0], f1_ = F1[0][0];
        sv[0][t] = pack2(e30 * __expf(f0_), e30 * __expf(f1_));
        GOLD(0, 0, f0_, f1_);
        __syncthreads();
    }
    STEP(0, 1, 0, 1, false);
    STEP(0, 2, 1, 0, false);
    STEP(0, 3, 0, 1, true);

    // Main loop: groups 1..255 in a 3-phase rotation; loads 2 groups ahead.
#pragma unroll 1
    for (int it = 0; it < 85; ++it) {
        const int gg = 1 + it * 3;
        PF(0, gg + 2);
        GROUP(1);
        PF(1, gg + 3);
        GROUP(2);
        PF(2, gg + 4);
        GROUP(0);
    }

#undef PF
#undef GOLD
#undef STEP
#undef GROUP

    // Epilogue. All groups end with v in sv[1].
    u64 v = sv[1][t];
    {
        const float es = __expf(__ldg(trans + STOP_ * T_ + t));
        v = mul2(v, pack2(es, es));
    }
#pragma unroll
    for (int o = 16; o > 0; o >>= 1) v = add2(v, __shfl_xor_sync(FULL_, v, o));
    u64 gep = pack2(ge0, ge1);
#pragma unroll
    for (int o = 16; o > 0; o >>= 1) gep = add2(gep, __shfl_xor_sync(FULL_, gep, o));

    if (t == 0) {
        float z0, z1, e0, e1;
        unpack2(v, z0, z1);
        unpack2(gep, e0, e1);
        const float LN2 = 0.6931471805599453f;
        const float a0 = __logf(z0) + (float)sc0 * LN2;
        const float a1 = __logf(z1) + (float)sc1 * LN2;
        const float go0 = gt0 + e0 + __ldg(trans + STOP_ * 32u + pv0);
        const float go1 = gt1 + e1 + __ldg(trans + STOP_ * 32u + pv1);
        *(float2*)(out + b0) = make_float2(a0 - go0, a1 - go1);
    }
}

__global__ void __launch_bounds__(32, 14) crf_fwd(const float* __restrict__ feats,
                                                  const float* __restrict__ trans,
                                                  const unsigned* __restrict__ tagw,
                                                  float* __restrict__ out) {
    __shared__ __align__(16) u64 sv[2][32];
    // Tag dtype detection: int64 tags (values < 30) have all-zero odd words.
    unsigned oddw = __ldg(tagw + 2 * threadIdx.x + 1);
    if (__any_sync(FULL_, oddw != 0)) {
        crf_body<1>(feats, trans, tagw, out, sv);  // int32 tags
    } else {
        crf_body<2>(feats, trans, tagw, out, sv);  // int64 tags
    }
}

}  // namespace

extern "C" void kernel_launch(void* const* d_in, const int* in_sizes, int n_in,
                              void* d_out, int out_size) {
    const float* feats = (const float*)d_in[0];
    const float* trans = (const float*)d_in[1];
    const unsigned* tagw = (const unsigned*)d_in[2];
    float* out = (float*)d_out;

    const int B = in_sizes[2] / L_;  // element count = B*L for either tag dtype
    crf_fwd<<<B / 2, 32>>>(feats, trans, tagw, out);
}